// round 14
// baseline (speedup 1.0000x reference)
#include <cuda_runtime.h>
#include <cuda_bf16.h>
#include <math.h>

// Problem dims (fixed by dataset)
#define T_TOK 4096
#define DIM   2048
#define IDIM  1024
#define NEXP  32
#define TOPK  4
#define ALPHA 7.0f
#define H_ROWS (T_TOK*TOPK + T_TOK)   // 20480
#define STAGES 3

// -------- device scratch --------
__device__ int   g_counts[NEXP];
__device__ int   g_offsets[NEXP];
__device__ int   g_done;
__device__ int   g_etok[NEXP * T_TOK];
__device__ float g_ew[NEXP * T_TOK];
__device__ int   g_tki[T_TOK * TOPK];
__device__ float g_tkw[T_TOK * TOPK];
__device__ float g_H[(size_t)H_ROWS * IDIM];   // tf32 RNA-rounded intermediate
__device__ float g_X[(size_t)T_TOK * DIM];     // tf32 RNA-rounded hidden

// -------- helpers --------
__device__ __forceinline__ unsigned f2tf32(float f) {
    unsigned r;
    asm("cvt.rna.tf32.f32 %0, %1;" : "=r"(r) : "f"(f));
    return r;
}
// RNA-equivalent for mma consumption: tensor core ignores low 13 bits of a tf32
// operand, so bits+0x1000 (carry rounds kept mantissa, ties away) == cvt.rna.
__device__ __forceinline__ unsigned rnabits(float f) {
    return __float_as_uint(f) + 0x1000u;
}

__device__ __forceinline__ void cpa16(float* smem_dst, const float* gsrc, bool pred) {
    unsigned s = (unsigned)__cvta_generic_to_shared(smem_dst);
    int sz = pred ? 16 : 0;
    asm volatile("cp.async.cg.shared.global [%0], [%1], 16, %2;\n"
                 :: "r"(s), "l"(gsrc), "r"(sz));
}
__device__ __forceinline__ void cpa_commit() {
    asm volatile("cp.async.commit_group;\n");
}
template<int N>
__device__ __forceinline__ void cpa_wait() {
    asm volatile("cp.async.wait_group %0;\n" :: "n"(N));
}
// vectorized fire-and-forget reduction (PTX 8.1+, sm_90+)
__device__ __forceinline__ void red2(float* p, float v0, float v1) {
    asm volatile("red.global.add.v2.f32 [%0], {%1, %2};"
                 :: "l"(p), "f"(v0), "f"(v1) : "memory");
}

// swizzled smem addressing: tiles are [rows][32] floats; xor-swizzle the float4
// slot by (row & 7) -> conflict-free LDS.
__device__ __forceinline__ int swz(int row, int col) {
    return row * 32 + (((col >> 2) ^ (row & 7)) << 2) + (col & 3);
}
__device__ __forceinline__ int swz4(int row, int c4) {
    return row * 32 + ((c4 ^ (row & 7)) << 2);
}

__device__ __forceinline__ void mma8(float* c, const unsigned* a, const unsigned* b) {
    asm volatile(
        "mma.sync.aligned.m16n8k8.row.col.f32.tf32.tf32.f32 "
        "{%0,%1,%2,%3}, {%4,%5,%6,%7}, {%8,%9}, {%0,%1,%2,%3};\n"
        : "+f"(c[0]), "+f"(c[1]), "+f"(c[2]), "+f"(c[3])
        : "r"(a[0]), "r"(a[1]), "r"(a[2]), "r"(a[3]), "r"(b[0]), "r"(b[1]));
}

// ================= Router (+ fused hidden rounding into g_X) =================
__global__ __launch_bounds__(256) void router_kernel(
    const float* __restrict__ x, const float* __restrict__ rw,
    const float* __restrict__ bias)
{
    int t = blockIdx.x;
    const float4* xr = (const float4*)(x + (size_t)t * DIM);
    __shared__ float logits[NEXP];
    int lane = threadIdx.x & 31, warp = threadIdx.x >> 5;

    #pragma unroll
    for (int it = 0; it < 4; it++) {
        int e = warp + it * 8;
        const float4* w = (const float4*)(rw + (size_t)e * DIM);
        float s = 0.f;
        for (int i = lane; i < DIM / 4; i += 32) {
            float4 xv = xr[i], wv = w[i];
            s += xv.x * wv.x + xv.y * wv.y + xv.z * wv.z + xv.w * wv.w;
        }
        #pragma unroll
        for (int o = 16; o; o >>= 1) s += __shfl_xor_sync(0xffffffffu, s, o);
        if (lane == 0) logits[e] = s;
    }

    // fused round_x: rows are L1-hot from the dot products above
    {
        float4* xo = (float4*)(g_X + (size_t)t * DIM);
        #pragma unroll
        for (int i = threadIdx.x; i < DIM / 4; i += 256) {
            float4 v = xr[i];
            v.x = __uint_as_float(f2tf32(v.x));
            v.y = __uint_as_float(f2tf32(v.y));
            v.z = __uint_as_float(f2tf32(v.z));
            v.w = __uint_as_float(f2tf32(v.w));
            xo[i] = v;
        }
    }
    __syncthreads();

    if (warp == 0) {
        float lg = logits[lane];
        float sp = (lg > 20.f) ? lg : log1pf(expf(lg));
        float score = sqrtf(sp);
        float cur = score + bias[lane];   // bias only for selection
        int   sel[TOPK];
        float sw[TOPK];
        float ssum = 0.f;
        #pragma unroll
        for (int k = 0; k < TOPK; k++) {
            float v = cur; int idx = lane;
            #pragma unroll
            for (int o = 16; o; o >>= 1) {
                float v2 = __shfl_xor_sync(0xffffffffu, v, o);
                int   i2 = __shfl_xor_sync(0xffffffffu, idx, o);
                if (v2 > v || (v2 == v && i2 < idx)) { v = v2; idx = i2; }
            }
            sel[k] = idx;
            float sc = __shfl_sync(0xffffffffu, score, idx);
            sw[k] = sc; ssum += sc;
            if (lane == idx) cur = -1e30f;
        }
        if (lane < TOPK) {
            g_tki[t * TOPK + lane] = sel[lane];
            g_tkw[t * TOPK + lane] = sw[lane] / (ssum + 1e-20f);
        }
    }
}

// ================= Stable per-expert gather (+ fused offsets) =================
__global__ __launch_bounds__(256) void gather_kernel()
{
    int e = blockIdx.x;
    __shared__ int warp_sums[8];
    __shared__ int base_s;
    int tid = threadIdx.x, lane = tid & 31, warp = tid >> 5;
    if (tid == 0) base_s = 0;
    __syncthreads();
    for (int c = 0; c < T_TOK * TOPK; c += 256) {
        int i = c + tid;
        int match = (g_tki[i] == e);
        unsigned bal = __ballot_sync(0xffffffffu, match);
        if (lane == 0) warp_sums[warp] = __popc(bal);
        __syncthreads();
        int off = 0, tot = 0;
        #pragma unroll
        for (int w = 0; w < 8; w++) { if (w < warp) off += warp_sums[w]; tot += warp_sums[w]; }
        int myb = base_s;
        if (match) {
            int pos = myb + off + __popc(bal & ((1u << lane) - 1u));
            g_etok[e * T_TOK + pos] = i >> 2;
            g_ew[e * T_TOK + pos]   = g_tkw[i];
        }
        __syncthreads();
        if (tid == 0) base_s = myb + tot;
        __syncthreads();
    }
    if (tid == 0) {
        g_counts[e] = base_s;
        __threadfence();
        int done = atomicAdd(&g_done, 1);
        if (done == NEXP - 1) {          // last block: compute offsets, reset flag
            g_done = 0;                  // deterministic across graph replays
            int s = 0;
            #pragma unroll
            for (int k = 0; k < NEXP; k++) { g_offsets[k] = s; s += g_counts[k]; }
        }
    }
}

// ================= Gate+Up grouped GEMM (R13, unchanged) =================
// BM=128, BN=64 (each of G and U), BK=32. 8 warps as 4x2; warp tile 32x32/matrix.
// 2 CTAs/SM. A from pre-rounded g_X (raw bits); weights rounded via +0x1000.
__global__ __launch_bounds__(256, 2) void gemm_gateup(
    const float* __restrict__ gate_w, const float* __restrict__ up_w,
    const float* __restrict__ sgate,  const float* __restrict__ sup)
{
    int e = blockIdx.z;
    int nrows = (e == NEXP) ? T_TOK : g_counts[e];
    int mt = blockIdx.y;
    if (mt * 128 >= nrows) return;
    int nt = blockIdx.x;   // 16 tiles of 64 over I

    extern __shared__ float smem[];
    float* As = smem;                       // STAGES * 4096
    float* Bg = As + STAGES * 4096;         // STAGES * 2048
    float* Bu = Bg + STAGES * 2048;         // STAGES * 2048
    __shared__ int toks[128];

    int tid = threadIdx.x, lane = tid & 31, warp = tid >> 5;
    int wm = warp >> 1, wn = warp & 1;

    if (tid < 128) {
        int m = mt * 128 + tid;
        toks[tid] = (m < nrows) ? ((e == NEXP) ? m : g_etok[e * T_TOK + m]) : -1;
    }
    __syncthreads();

    const float* gbase = (e == NEXP) ? sgate : gate_w + (size_t)e * IDIM * DIM;
    const float* ubase = (e == NEXP) ? sup   : up_w   + (size_t)e * IDIM * DIM;

    auto load_stage = [&](int buf, int k0) {
        float* Ab  = As + buf * 4096;
        float* Bgb = Bg + buf * 2048;
        float* Bub = Bu + buf * 2048;
        #pragma unroll
        for (int it = 0; it < 4; it++) {
            int idx = tid + it * 256;
            int row = idx >> 3, c4 = idx & 7;
            int tok = toks[row];
            const float* src = g_X + (size_t)(tok < 0 ? 0 : tok) * DIM + k0 + c4 * 4;
            cpa16(Ab + swz4(row, c4), src, tok >= 0);
        }
        #pragma unroll
        for (int it = 0; it < 2; it++) {
            int idx = tid + it * 256;
            int row = idx >> 3, c4 = idx & 7;
            size_t off = (size_t)(nt * 64 + row) * DIM + k0 + c4 * 4;
            cpa16(Bgb + swz4(row, c4), gbase + off, true);
            cpa16(Bub + swz4(row, c4), ubase + off, true);
        }
    };

    float accG[2][4][4], accU[2][4][4];
    #pragma unroll
    for (int a = 0; a < 2; a++)
        #pragma unroll
        for (int b = 0; b < 4; b++)
            #pragma unroll
            for (int c = 0; c < 4; c++) { accG[a][b][c] = 0.f; accU[a][b][c] = 0.f; }

    const int KB = DIM / 32;  // 64
    #pragma unroll
    for (int s = 0; s < STAGES - 1; s++) { load_stage(s, s * 32); cpa_commit(); }

    for (int kb = 0; kb < KB; kb++) {
        cpa_wait<STAGES - 2>();
        __syncthreads();
        int nb = kb + STAGES - 1;
        if (nb < KB) load_stage(nb % STAGES, nb * 32);
        cpa_commit();

        int buf = kb % STAGES;
        const float* Ab  = As + buf * 4096;
        const float* Bgb = Bg + buf * 2048;
        const float* Bub = Bu + buf * 2048;

        #pragma unroll
        for (int ks = 0; ks < 4; ks++) {
            int kk = ks * 8;
            unsigned a[2][4], bg[4][2], bu[4][2];
            #pragma unroll
            for (int mi = 0; mi < 2; mi++) {
                int r = wm * 32 + mi * 16 + (lane >> 2);
                int c = kk + (lane & 3);
                a[mi][0] = __float_as_uint(Ab[swz(r,     c)]);
                a[mi][1] = __float_as_uint(Ab[swz(r + 8, c)]);
                a[mi][2] = __float_as_uint(Ab[swz(r,     c + 4)]);
                a[mi][3] = __float_as_uint(Ab[swz(r + 8, c + 4)]);
            }
            #pragma unroll
            for (int ni = 0; ni < 4; ni++) {
                int n = wn * 32 + ni * 8 + (lane >> 2);
                int c = kk + (lane & 3);
                bg[ni][0] = rnabits(Bgb[swz(n, c)]);  bg[ni][1] = rnabits(Bgb[swz(n, c + 4)]);
                bu[ni][0] = rnabits(Bub[swz(n, c)]);  bu[ni][1] = rnabits(Bub[swz(n, c + 4)]);
            }
            #pragma unroll
            for (int mi = 0; mi < 2; mi++)
                #pragma unroll
                for (int ni = 0; ni < 4; ni++) {
                    mma8(accG[mi][ni], a[mi], bg[ni]);
                    mma8(accU[mi][ni], a[mi], bu[ni]);
                }
        }
        __syncthreads();
    }

    int hbase = (e == NEXP) ? (T_TOK * TOPK) : g_offsets[e];
    #pragma unroll
    for (int mi = 0; mi < 2; mi++)
        #pragma unroll
        for (int ni = 0; ni < 4; ni++) {
            int col = nt * 64 + wn * 32 + ni * 8 + (lane & 3) * 2;
            #pragma unroll
            for (int half = 0; half < 2; half++) {
                int r = wm * 32 + mi * 16 + (lane >> 2) + half * 8;
                int m = mt * 128 + r;
                if (m < nrows) {
                    float g0 = fminf(fmaxf(accG[mi][ni][half * 2 + 0], -ALPHA), ALPHA);
                    float g1 = fminf(fmaxf(accG[mi][ni][half * 2 + 1], -ALPHA), ALPHA);
                    float u0 = fminf(fmaxf(accU[mi][ni][half * 2 + 0], -ALPHA), ALPHA);
                    float u1 = fminf(fmaxf(accU[mi][ni][half * 2 + 1], -ALPHA), ALPHA);
                    float h0 = g0 / (1.f + __expf(-g0)) * u0;
                    float h1 = g1 / (1.f + __expf(-g1)) * u1;
                    float2 hv;
                    hv.x = __uint_as_float(f2tf32(h0));  // pre-round: down GEMM skips cvt
                    hv.y = __uint_as_float(f2tf32(h1));
                    *(float2*)(g_H + (size_t)(hbase + m) * IDIM + col) = hv;
                }
            }
        }
}

// ================= Down grouped GEMM + weighted scatter (R13, unchanged) ======
// BM=128, BN=128, BK=32. 8 warps as 2x4; warp tile 64x32. 2 CTAs/SM.
__global__ __launch_bounds__(256, 2) void gemm_down(
    const float* __restrict__ down_w, const float* __restrict__ sdown,
    float* __restrict__ out)
{
    int e = blockIdx.z;
    int nrows = (e == NEXP) ? T_TOK : g_counts[e];
    int mt = blockIdx.y;
    if (mt * 128 >= nrows) return;
    int nt = blockIdx.x;   // 16 tiles of 128 over D

    extern __shared__ float smem[];
    float* Hs = smem;                 // STAGES * 4096
    float* Bs = Hs + STAGES * 4096;   // STAGES * 4096
    __shared__ int   toks[128];
    __shared__ float wts[128];

    int tid = threadIdx.x, lane = tid & 31, warp = tid >> 5;
    int wm = warp >> 2, wn = warp & 3;

    if (tid < 128) {
        int m = mt * 128 + tid;
        if (e == NEXP)      { toks[tid] = m;                       wts[tid] = 1.f; }
        else if (m < nrows) { toks[tid] = g_etok[e * T_TOK + m];   wts[tid] = g_ew[e * T_TOK + m]; }
        else                { toks[tid] = 0;                       wts[tid] = 0.f; }
    }
    __syncthreads();

    const float* dbase = (e == NEXP) ? sdown : down_w + (size_t)e * DIM * IDIM;
    int hbase = (e == NEXP) ? (T_TOK * TOPK) : g_offsets[e];

    auto load_stage = [&](int buf, int k0) {
        float* Hb = Hs + buf * 4096;
        float* Bb = Bs + buf * 4096;
        #pragma unroll
        for (int it = 0; it < 4; it++) {
            int idx = tid + it * 256;
            int row = idx >> 3, c4 = idx & 7;
            cpa16(Hb + swz4(row, c4),
                  g_H + (size_t)(hbase + mt * 128 + row) * IDIM + k0 + c4 * 4, true);
            cpa16(Bb + swz4(row, c4),
                  dbase + (size_t)(nt * 128 + row) * IDIM + k0 + c4 * 4, true);
        }
    };

    float acc[4][4][4];
    #pragma unroll
    for (int a = 0; a < 4; a++)
        #pragma unroll
        for (int b = 0; b < 4; b++)
            #pragma unroll
            for (int c = 0; c < 4; c++) acc[a][b][c] = 0.f;

    const int KB = IDIM / 32;  // 32
    #pragma unroll
    for (int s = 0; s < STAGES - 1; s++) { load_stage(s, s * 32); cpa_commit(); }

    for (int kb = 0; kb < KB; kb++) {
        cpa_wait<STAGES - 2>();
        __syncthreads();
        int nb = kb + STAGES - 1;
        if (nb < KB) load_stage(nb % STAGES, nb * 32);
        cpa_commit();

        int buf = kb % STAGES;
        const float* Hb = Hs + buf * 4096;
        const float* Bb = Bs + buf * 4096;

        #pragma unroll
        for (int ks = 0; ks < 4; ks++) {
            int kk = ks * 8;
            unsigned a[4][4], b[4][2];
            #pragma unroll
            for (int mi = 0; mi < 4; mi++) {
                int r = wm * 64 + mi * 16 + (lane >> 2);
                int c = kk + (lane & 3);
                a[mi][0] = __float_as_uint(Hb[swz(r,     c)]);
                a[mi][1] = __float_as_uint(Hb[swz(r + 8, c)]);
                a[mi][2] = __float_as_uint(Hb[swz(r,     c + 4)]);
                a[mi][3] = __float_as_uint(Hb[swz(r + 8, c + 4)]);
            }
            #pragma unroll
            for (int ni = 0; ni < 4; ni++) {
                int n = wn * 32 + ni * 8 + (lane >> 2);
                int c = kk + (lane & 3);
                b[ni][0] = rnabits(Bb[swz(n, c)]);
                b[ni][1] = rnabits(Bb[swz(n, c + 4)]);
            }
            #pragma unroll
            for (int mi = 0; mi < 4; mi++)
                #pragma unroll
                for (int ni = 0; ni < 4; ni++)
                    mma8(acc[mi][ni], a[mi], b[ni]);
        }
        __syncthreads();
    }

    #pragma unroll
    for (int mi = 0; mi < 4; mi++)
        #pragma unroll
        for (int half = 0; half < 2; half++) {
            int r = wm * 64 + mi * 16 + (lane >> 2) + half * 8;
            int m = mt * 128 + r;
            if (m < nrows) {
                int   tok = toks[r];
                float w   = wts[r];
                float* orow = out + (size_t)tok * DIM;
                #pragma unroll
                for (int ni = 0; ni < 4; ni++) {
                    int col = nt * 128 + wn * 32 + ni * 8 + (lane & 3) * 2;
                    red2(orow + col, w * acc[mi][ni][half * 2 + 0],
                                     w * acc[mi][ni][half * 2 + 1]);
                }
            }
        }
}

// ================= launch =================
extern "C" void kernel_launch(void* const* d_in, const int* in_sizes, int n_in,
                              void* d_out, int out_size)
{
    const float* hidden   = (const float*)d_in[0];
    const float* router_w = (const float*)d_in[1];
    const float* bias     = (const float*)d_in[2];
    const float* gate_w   = (const float*)d_in[3];
    const float* up_w     = (const float*)d_in[4];
    const float* down_w   = (const float*)d_in[5];
    const float* sgate    = (const float*)d_in[6];
    const float* sup      = (const float*)d_in[7];
    const float* sdown    = (const float*)d_in[8];
    float* out = (float*)d_out;

    const int smem_gu = STAGES * (4096 + 2048 + 2048) * 4;  // 96 KB
    const int smem_dn = STAGES * (4096 + 4096) * 4;          // 96 KB
    cudaFuncSetAttribute(gemm_gateup, cudaFuncAttributeMaxDynamicSharedMemorySize, smem_gu);
    cudaFuncSetAttribute(gemm_down,   cudaFuncAttributeMaxDynamicSharedMemorySize, smem_dn);

    cudaMemsetAsync(out, 0, (size_t)T_TOK * DIM * sizeof(float));
    router_kernel<<<T_TOK, 256>>>(hidden, router_w, bias);   // also rounds hidden -> g_X
    gather_kernel<<<NEXP, 256>>>();                          // also computes offsets
    gemm_gateup<<<dim3(IDIM / 64, T_TOK / 128, NEXP + 1), 256, smem_gu>>>(gate_w, up_w, sgate, sup);
    gemm_down<<<dim3(DIM / 128, T_TOK / 128, NEXP + 1), 256, smem_dn>>>(down_w, sdown, out);
}

// round 15
// speedup vs baseline: 1.0115x; 1.0115x over previous
#include <cuda_runtime.h>
#include <cuda_bf16.h>
#include <math.h>

// Problem dims (fixed by dataset)
#define T_TOK 4096
#define DIM   2048
#define IDIM  1024
#define NEXP  32
#define TOPK  4
#define ALPHA 7.0f
#define H_ROWS (T_TOK*TOPK + T_TOK)   // 20480
#define STAGES 3

// -------- device scratch --------
__device__ int   g_counts[NEXP];
__device__ int   g_offsets[NEXP];
__device__ int   g_etok[NEXP * T_TOK];
__device__ float g_ew[NEXP * T_TOK];
__device__ int   g_tki[T_TOK * TOPK];
__device__ float g_tkw[T_TOK * TOPK];
__device__ float g_H[(size_t)H_ROWS * IDIM];   // tf32 RNA-rounded intermediate
__device__ float g_X[(size_t)T_TOK * DIM];     // tf32 RNA-rounded hidden

// -------- helpers --------
__device__ __forceinline__ unsigned f2tf32(float f) {
    unsigned r;
    asm("cvt.rna.tf32.f32 %0, %1;" : "=r"(r) : "f"(f));
    return r;
}
// RNA-equivalent for mma consumption: tensor core ignores low 13 bits of a tf32
// operand, so bits+0x1000 (carry rounds kept mantissa, ties away) == cvt.rna.
__device__ __forceinline__ unsigned rnabits(float f) {
    return __float_as_uint(f) + 0x1000u;
}

__device__ __forceinline__ void cpa16(float* smem_dst, const float* gsrc, bool pred) {
    unsigned s = (unsigned)__cvta_generic_to_shared(smem_dst);
    int sz = pred ? 16 : 0;
    asm volatile("cp.async.cg.shared.global [%0], [%1], 16, %2;\n"
                 :: "r"(s), "l"(gsrc), "r"(sz));
}
__device__ __forceinline__ void cpa_commit() {
    asm volatile("cp.async.commit_group;\n");
}
template<int N>
__device__ __forceinline__ void cpa_wait() {
    asm volatile("cp.async.wait_group %0;\n" :: "n"(N));
}
// vectorized fire-and-forget reduction (PTX 8.1+, sm_90+)
__device__ __forceinline__ void red2(float* p, float v0, float v1) {
    asm volatile("red.global.add.v2.f32 [%0], {%1, %2};"
                 :: "l"(p), "f"(v0), "f"(v1) : "memory");
}

// swizzled smem addressing: tiles are [rows][32] floats; xor-swizzle the float4
// slot by (row & 7) -> conflict-free LDS.
__device__ __forceinline__ int swz(int row, int col) {
    return row * 32 + (((col >> 2) ^ (row & 7)) << 2) + (col & 3);
}
__device__ __forceinline__ int swz4(int row, int c4) {
    return row * 32 + ((c4 ^ (row & 7)) << 2);
}

__device__ __forceinline__ void mma8(float* c, const unsigned* a, const unsigned* b) {
    asm volatile(
        "mma.sync.aligned.m16n8k8.row.col.f32.tf32.tf32.f32 "
        "{%0,%1,%2,%3}, {%4,%5,%6,%7}, {%8,%9}, {%0,%1,%2,%3};\n"
        : "+f"(c[0]), "+f"(c[1]), "+f"(c[2]), "+f"(c[3])
        : "r"(a[0]), "r"(a[1]), "r"(a[2]), "r"(a[3]), "r"(b[0]), "r"(b[1]));
}

// ================= prepass: RNA-round hidden into g_X =================
__global__ __launch_bounds__(256) void round_x(const float* __restrict__ x) {
    int i = blockIdx.x * 256 + threadIdx.x;
    float4 v = ((const float4*)x)[i];
    v.x = __uint_as_float(f2tf32(v.x));
    v.y = __uint_as_float(f2tf32(v.y));
    v.z = __uint_as_float(f2tf32(v.z));
    v.w = __uint_as_float(f2tf32(v.w));
    ((float4*)g_X)[i] = v;
}

// ================= Router =================
__global__ __launch_bounds__(256) void router_kernel(
    const float* __restrict__ x, const float* __restrict__ rw,
    const float* __restrict__ bias)
{
    int t = blockIdx.x;
    const float4* xr = (const float4*)(x + (size_t)t * DIM);
    __shared__ float logits[NEXP];
    int lane = threadIdx.x & 31, warp = threadIdx.x >> 5;

    #pragma unroll
    for (int it = 0; it < 4; it++) {
        int e = warp + it * 8;
        const float4* w = (const float4*)(rw + (size_t)e * DIM);
        float s = 0.f;
        for (int i = lane; i < DIM / 4; i += 32) {
            float4 xv = xr[i], wv = w[i];
            s += xv.x * wv.x + xv.y * wv.y + xv.z * wv.z + xv.w * wv.w;
        }
        #pragma unroll
        for (int o = 16; o; o >>= 1) s += __shfl_xor_sync(0xffffffffu, s, o);
        if (lane == 0) logits[e] = s;
    }
    __syncthreads();

    if (warp == 0) {
        float lg = logits[lane];
        float sp = (lg > 20.f) ? lg : log1pf(expf(lg));
        float score = sqrtf(sp);
        float cur = score + bias[lane];   // bias only for selection
        int   sel[TOPK];
        float sw[TOPK];
        float ssum = 0.f;
        #pragma unroll
        for (int k = 0; k < TOPK; k++) {
            float v = cur; int idx = lane;
            #pragma unroll
            for (int o = 16; o; o >>= 1) {
                float v2 = __shfl_xor_sync(0xffffffffu, v, o);
                int   i2 = __shfl_xor_sync(0xffffffffu, idx, o);
                if (v2 > v || (v2 == v && i2 < idx)) { v = v2; idx = i2; }
            }
            sel[k] = idx;
            float sc = __shfl_sync(0xffffffffu, score, idx);
            sw[k] = sc; ssum += sc;
            if (lane == idx) cur = -1e30f;
        }
        if (lane < TOPK) {
            g_tki[t * TOPK + lane] = sel[lane];
            g_tkw[t * TOPK + lane] = sw[lane] / (ssum + 1e-20f);
        }
    }
}

// ================= Stable per-expert gather =================
__global__ __launch_bounds__(256) void gather_kernel()
{
    int e = blockIdx.x;
    __shared__ int warp_sums[8];
    __shared__ int base_s;
    int tid = threadIdx.x, lane = tid & 31, warp = tid >> 5;
    if (tid == 0) base_s = 0;
    __syncthreads();
    for (int c = 0; c < T_TOK * TOPK; c += 256) {
        int i = c + tid;
        int match = (g_tki[i] == e);
        unsigned bal = __ballot_sync(0xffffffffu, match);
        if (lane == 0) warp_sums[warp] = __popc(bal);
        __syncthreads();
        int off = 0, tot = 0;
        #pragma unroll
        for (int w = 0; w < 8; w++) { if (w < warp) off += warp_sums[w]; tot += warp_sums[w]; }
        int myb = base_s;
        if (match) {
            int pos = myb + off + __popc(bal & ((1u << lane) - 1u));
            g_etok[e * T_TOK + pos] = i >> 2;
            g_ew[e * T_TOK + pos]   = g_tkw[i];
        }
        __syncthreads();
        if (tid == 0) base_s = myb + tot;
        __syncthreads();
    }
    if (tid == 0) g_counts[e] = base_s;
}

__global__ void offsets_kernel()
{
    if (threadIdx.x == 0) {
        int s = 0;
        for (int e = 0; e < NEXP; e++) { g_offsets[e] = s; s += g_counts[e]; }
    }
}

// ================= Gate+Up grouped GEMM (single-barrier pipeline) =================
// BM=128, BN=64 (each of G and U), BK=32. 8 warps as 4x2; warp tile 32x32/matrix.
// 2 CTAs/SM. A from pre-rounded g_X (raw bits); weights rounded via +0x1000.
// One __syncthreads per K-block: the leading barrier of iteration kb+1 protects
// stage kb%3 from being overwritten (it is the stage iteration kb+1 loads into).
__global__ __launch_bounds__(256, 2) void gemm_gateup(
    const float* __restrict__ gate_w, const float* __restrict__ up_w,
    const float* __restrict__ sgate,  const float* __restrict__ sup)
{
    int e = blockIdx.z;
    int nrows = (e == NEXP) ? T_TOK : g_counts[e];
    int mt = blockIdx.y;
    if (mt * 128 >= nrows) return;
    int nt = blockIdx.x;   // 16 tiles of 64 over I

    extern __shared__ float smem[];
    float* As = smem;                       // STAGES * 4096
    float* Bg = As + STAGES * 4096;         // STAGES * 2048
    float* Bu = Bg + STAGES * 2048;         // STAGES * 2048
    __shared__ int toks[128];

    int tid = threadIdx.x, lane = tid & 31, warp = tid >> 5;
    int wm = warp >> 1, wn = warp & 1;

    if (tid < 128) {
        int m = mt * 128 + tid;
        toks[tid] = (m < nrows) ? ((e == NEXP) ? m : g_etok[e * T_TOK + m]) : -1;
    }
    __syncthreads();

    const float* gbase = (e == NEXP) ? sgate : gate_w + (size_t)e * IDIM * DIM;
    const float* ubase = (e == NEXP) ? sup   : up_w   + (size_t)e * IDIM * DIM;

    auto load_stage = [&](int buf, int k0) {
        float* Ab  = As + buf * 4096;
        float* Bgb = Bg + buf * 2048;
        float* Bub = Bu + buf * 2048;
        #pragma unroll
        for (int it = 0; it < 4; it++) {
            int idx = tid + it * 256;
            int row = idx >> 3, c4 = idx & 7;
            int tok = toks[row];
            const float* src = g_X + (size_t)(tok < 0 ? 0 : tok) * DIM + k0 + c4 * 4;
            cpa16(Ab + swz4(row, c4), src, tok >= 0);
        }
        #pragma unroll
        for (int it = 0; it < 2; it++) {
            int idx = tid + it * 256;
            int row = idx >> 3, c4 = idx & 7;
            size_t off = (size_t)(nt * 64 + row) * DIM + k0 + c4 * 4;
            cpa16(Bgb + swz4(row, c4), gbase + off, true);
            cpa16(Bub + swz4(row, c4), ubase + off, true);
        }
    };

    float accG[2][4][4], accU[2][4][4];
    #pragma unroll
    for (int a = 0; a < 2; a++)
        #pragma unroll
        for (int b = 0; b < 4; b++)
            #pragma unroll
            for (int c = 0; c < 4; c++) { accG[a][b][c] = 0.f; accU[a][b][c] = 0.f; }

    const int KB = DIM / 32;  // 64
    #pragma unroll
    for (int s = 0; s < STAGES - 1; s++) { load_stage(s, s * 32); cpa_commit(); }

    for (int kb = 0; kb < KB; kb++) {
        cpa_wait<STAGES - 2>();
        __syncthreads();
        int nb = kb + STAGES - 1;
        if (nb < KB) load_stage(nb % STAGES, nb * 32);
        cpa_commit();

        int buf = kb % STAGES;
        const float* Ab  = As + buf * 4096;
        const float* Bgb = Bg + buf * 2048;
        const float* Bub = Bu + buf * 2048;

        #pragma unroll
        for (int ks = 0; ks < 4; ks++) {
            int kk = ks * 8;
            unsigned a[2][4], bg[4][2], bu[4][2];
            #pragma unroll
            for (int mi = 0; mi < 2; mi++) {
                int r = wm * 32 + mi * 16 + (lane >> 2);
                int c = kk + (lane & 3);
                a[mi][0] = __float_as_uint(Ab[swz(r,     c)]);
                a[mi][1] = __float_as_uint(Ab[swz(r + 8, c)]);
                a[mi][2] = __float_as_uint(Ab[swz(r,     c + 4)]);
                a[mi][3] = __float_as_uint(Ab[swz(r + 8, c + 4)]);
            }
            #pragma unroll
            for (int ni = 0; ni < 4; ni++) {
                int n = wn * 32 + ni * 8 + (lane >> 2);
                int c = kk + (lane & 3);
                bg[ni][0] = rnabits(Bgb[swz(n, c)]);  bg[ni][1] = rnabits(Bgb[swz(n, c + 4)]);
                bu[ni][0] = rnabits(Bub[swz(n, c)]);  bu[ni][1] = rnabits(Bub[swz(n, c + 4)]);
            }
            #pragma unroll
            for (int mi = 0; mi < 2; mi++)
                #pragma unroll
                for (int ni = 0; ni < 4; ni++) {
                    mma8(accG[mi][ni], a[mi], bg[ni]);
                    mma8(accU[mi][ni], a[mi], bu[ni]);
                }
        }
        // no trailing __syncthreads: next iteration's leading barrier protects
        // this stage from overwrite (see kernel comment).
    }

    int hbase = (e == NEXP) ? (T_TOK * TOPK) : g_offsets[e];
    #pragma unroll
    for (int mi = 0; mi < 2; mi++)
        #pragma unroll
        for (int ni = 0; ni < 4; ni++) {
            int col = nt * 64 + wn * 32 + ni * 8 + (lane & 3) * 2;
            #pragma unroll
            for (int half = 0; half < 2; half++) {
                int r = wm * 32 + mi * 16 + (lane >> 2) + half * 8;
                int m = mt * 128 + r;
                if (m < nrows) {
                    float g0 = fminf(fmaxf(accG[mi][ni][half * 2 + 0], -ALPHA), ALPHA);
                    float g1 = fminf(fmaxf(accG[mi][ni][half * 2 + 1], -ALPHA), ALPHA);
                    float u0 = fminf(fmaxf(accU[mi][ni][half * 2 + 0], -ALPHA), ALPHA);
                    float u1 = fminf(fmaxf(accU[mi][ni][half * 2 + 1], -ALPHA), ALPHA);
                    float h0 = g0 / (1.f + __expf(-g0)) * u0;
                    float h1 = g1 / (1.f + __expf(-g1)) * u1;
                    float2 hv;
                    hv.x = __uint_as_float(f2tf32(h0));  // pre-round: down GEMM skips cvt
                    hv.y = __uint_as_float(f2tf32(h1));
                    *(float2*)(g_H + (size_t)(hbase + m) * IDIM + col) = hv;
                }
            }
        }
}

// ================= Down grouped GEMM + weighted scatter (single-barrier) ======
// BM=128, BN=128, BK=32. 8 warps as 2x4; warp tile 64x32. 2 CTAs/SM.
__global__ __launch_bounds__(256, 2) void gemm_down(
    const float* __restrict__ down_w, const float* __restrict__ sdown,
    float* __restrict__ out)
{
    int e = blockIdx.z;
    int nrows = (e == NEXP) ? T_TOK : g_counts[e];
    int mt = blockIdx.y;
    if (mt * 128 >= nrows) return;
    int nt = blockIdx.x;   // 16 tiles of 128 over D

    extern __shared__ float smem[];
    float* Hs = smem;                 // STAGES * 4096
    float* Bs = Hs + STAGES * 4096;   // STAGES * 4096
    __shared__ int   toks[128];
    __shared__ float wts[128];

    int tid = threadIdx.x, lane = tid & 31, warp = tid >> 5;
    int wm = warp >> 2, wn = warp & 3;

    if (tid < 128) {
        int m = mt * 128 + tid;
        if (e == NEXP)      { toks[tid] = m;                       wts[tid] = 1.f; }
        else if (m < nrows) { toks[tid] = g_etok[e * T_TOK + m];   wts[tid] = g_ew[e * T_TOK + m]; }
        else                { toks[tid] = 0;                       wts[tid] = 0.f; }
    }
    __syncthreads();

    const float* dbase = (e == NEXP) ? sdown : down_w + (size_t)e * DIM * IDIM;
    int hbase = (e == NEXP) ? (T_TOK * TOPK) : g_offsets[e];

    auto load_stage = [&](int buf, int k0) {
        float* Hb = Hs + buf * 4096;
        float* Bb = Bs + buf * 4096;
        #pragma unroll
        for (int it = 0; it < 4; it++) {
            int idx = tid + it * 256;
            int row = idx >> 3, c4 = idx & 7;
            cpa16(Hb + swz4(row, c4),
                  g_H + (size_t)(hbase + mt * 128 + row) * IDIM + k0 + c4 * 4, true);
            cpa16(Bb + swz4(row, c4),
                  dbase + (size_t)(nt * 128 + row) * IDIM + k0 + c4 * 4, true);
        }
    };

    float acc[4][4][4];
    #pragma unroll
    for (int a = 0; a < 4; a++)
        #pragma unroll
        for (int b = 0; b < 4; b++)
            #pragma unroll
            for (int c = 0; c < 4; c++) acc[a][b][c] = 0.f;

    const int KB = IDIM / 32;  // 32
    #pragma unroll
    for (int s = 0; s < STAGES - 1; s++) { load_stage(s, s * 32); cpa_commit(); }

    for (int kb = 0; kb < KB; kb++) {
        cpa_wait<STAGES - 2>();
        __syncthreads();
        int nb = kb + STAGES - 1;
        if (nb < KB) load_stage(nb % STAGES, nb * 32);
        cpa_commit();

        int buf = kb % STAGES;
        const float* Hb = Hs + buf * 4096;
        const float* Bb = Bs + buf * 4096;

        #pragma unroll
        for (int ks = 0; ks < 4; ks++) {
            int kk = ks * 8;
            unsigned a[4][4], b[4][2];
            #pragma unroll
            for (int mi = 0; mi < 4; mi++) {
                int r = wm * 64 + mi * 16 + (lane >> 2);
                int c = kk + (lane & 3);
                a[mi][0] = __float_as_uint(Hb[swz(r,     c)]);
                a[mi][1] = __float_as_uint(Hb[swz(r + 8, c)]);
                a[mi][2] = __float_as_uint(Hb[swz(r,     c + 4)]);
                a[mi][3] = __float_as_uint(Hb[swz(r + 8, c + 4)]);
            }
            #pragma unroll
            for (int ni = 0; ni < 4; ni++) {
                int n = wn * 32 + ni * 8 + (lane >> 2);
                int c = kk + (lane & 3);
                b[ni][0] = rnabits(Bb[swz(n, c)]);
                b[ni][1] = rnabits(Bb[swz(n, c + 4)]);
            }
            #pragma unroll
            for (int mi = 0; mi < 4; mi++)
                #pragma unroll
                for (int ni = 0; ni < 4; ni++)
                    mma8(acc[mi][ni], a[mi], b[ni]);
        }
        // no trailing __syncthreads (see gemm_gateup comment).
    }

    #pragma unroll
    for (int mi = 0; mi < 4; mi++)
        #pragma unroll
        for (int half = 0; half < 2; half++) {
            int r = wm * 64 + mi * 16 + (lane >> 2) + half * 8;
            int m = mt * 128 + r;
            if (m < nrows) {
                int   tok = toks[r];
                float w   = wts[r];
                float* orow = out + (size_t)tok * DIM;
                #pragma unroll
                for (int ni = 0; ni < 4; ni++) {
                    int col = nt * 128 + wn * 32 + ni * 8 + (lane & 3) * 2;
                    red2(orow + col, w * acc[mi][ni][half * 2 + 0],
                                     w * acc[mi][ni][half * 2 + 1]);
                }
            }
        }
}

// ================= launch =================
extern "C" void kernel_launch(void* const* d_in, const int* in_sizes, int n_in,
                              void* d_out, int out_size)
{
    const float* hidden   = (const float*)d_in[0];
    const float* router_w = (const float*)d_in[1];
    const float* bias     = (const float*)d_in[2];
    const float* gate_w   = (const float*)d_in[3];
    const float* up_w     = (const float*)d_in[4];
    const float* down_w   = (const float*)d_in[5];
    const float* sgate    = (const float*)d_in[6];
    const float* sup      = (const float*)d_in[7];
    const float* sdown    = (const float*)d_in[8];
    float* out = (float*)d_out;

    const int smem_gu = STAGES * (4096 + 2048 + 2048) * 4;  // 96 KB
    const int smem_dn = STAGES * (4096 + 4096) * 4;          // 96 KB
    cudaFuncSetAttribute(gemm_gateup, cudaFuncAttributeMaxDynamicSharedMemorySize, smem_gu);
    cudaFuncSetAttribute(gemm_down,   cudaFuncAttributeMaxDynamicSharedMemorySize, smem_dn);

    cudaMemsetAsync(out, 0, (size_t)T_TOK * DIM * sizeof(float));
    round_x<<<T_TOK * DIM / 4 / 256, 256>>>(hidden);
    router_kernel<<<T_TOK, 256>>>(hidden, router_w, bias);
    gather_kernel<<<NEXP, 256>>>();
    offsets_kernel<<<1, 32>>>();
    gemm_gateup<<<dim3(IDIM / 64, T_TOK / 128, NEXP + 1), 256, smem_gu>>>(gate_w, up_w, sgate, sup);
    gemm_down<<<dim3(DIM / 128, T_TOK / 128, NEXP + 1), 256, smem_dn>>>(down_w, sdown, out);
}